// round 1
// baseline (speedup 1.0000x reference)
#include <cuda_runtime.h>
#include <math.h>

#define NB 32
#define NA 5
#define NC 20
#define NH 64
#define NW 64
#define NT 50
#define HW (NH*NW)                  // 4096
#define CELLS_PER_B (NA*HW)         // 20480
#define NCELL (NB*CELLS_PER_B)      // 655360
#define NCH (5+NC)                  // 25

// Per-target scratch (device globals — no allocation allowed)
__device__ int    g_cell[NB*NT];
__device__ float  g_gl[NB*NT], g_gr[NB*NT], g_gt[NB*NT], g_gb[NB*NT], g_ga[NB*NT];
__device__ float  g_tx[NB*NT], g_ty[NB*NT], g_twv[NB*NT], g_thv[NB*NT];
__device__ int    g_tcls[NB*NT];
__device__ double g_loss;

__global__ void k_zero() {
    if (threadIdx.x == 0) g_loss = 0.0;
}

// One block per batch; threads 0..49 handle the 50 targets.
__global__ void k_prep(const float* __restrict__ target,
                       const float* __restrict__ anchors) {
    int b = blockIdx.x;
    int t = threadIdx.x;
    if (t >= NT) return;
    int idx = b*NT + t;
    const float* tg = target + (size_t)(b*NT + t)*5;
    float cls = tg[0], xn = tg[1], yn = tg[2], wn = tg[3], hn = tg[4];
    if (!(xn > 0.0f)) { g_cell[idx] = -1; return; }
    float gx = xn * (float)NW, gy = yn * (float)NH;
    float gw = wn * (float)NW, gh = hn * (float)NH;

    // best anchor by wh-IoU (first max wins, like argmax)
    int best = 0; float bi = -1.0f, baw = anchors[0], bah = anchors[1];
    #pragma unroll
    for (int a = 0; a < NA; a++) {
        float aw = anchors[2*a], ah = anchors[2*a+1];
        float inter = fminf(gw, aw) * fminf(gh, ah);
        float uni = fmaxf(gw*gh + aw*ah - inter, 1e-10f);
        float iou = inter / uni;
        if (iou > bi) { bi = iou; best = a; baw = aw; bah = ah; }
    }
    int gi = min(max((int)floorf(gx), 0), NW-1);
    int gj = min(max((int)floorf(gy), 0), NH-1);
    g_cell[idx] = ((b*NA + best)*NH + gj)*NW + gi;
    g_gl[idx] = gx - 0.5f*gw;  g_gr[idx] = gx + 0.5f*gw;
    g_gt[idx] = gy - 0.5f*gh;  g_gb[idx] = gy + 0.5f*gh;
    g_ga[idx] = gw * gh;
    g_tx[idx] = gx - (float)gi;
    g_ty[idx] = gy - (float)gj;
    g_twv[idx] = logf(fmaxf(gw, 1e-10f) / baw);
    g_thv[idx] = logf(fmaxf(gh, 1e-10f) / bah);
    g_tcls[idx] = (int)cls;
}

// One thread per cell. Blocks of 256 -> each block is entirely inside one batch
// (20480 % 256 == 0), so SMEM-staged target records are uniform per block.
__global__ void __launch_bounds__(256) k_main(const float* __restrict__ out,
                                              const float* __restrict__ anchors) {
    __shared__ int   s_cell[NT];
    __shared__ float s_gl[NT], s_gr[NT], s_gt[NT], s_gb[NT], s_ga[NT];
    __shared__ double s_ws[8];

    int gid = blockIdx.x * 256 + threadIdx.x;
    int b = gid / CELLS_PER_B;
    int within = gid - b * CELLS_PER_B;
    int a = within >> 12;        // / 4096
    int ji = within & 4095;
    int j = ji >> 6, i = ji & 63;

    if (threadIdx.x < NT) {
        int r = b*NT + threadIdx.x;
        s_cell[threadIdx.x] = g_cell[r];
        s_gl[threadIdx.x] = g_gl[r];  s_gr[threadIdx.x] = g_gr[r];
        s_gt[threadIdx.x] = g_gt[r];  s_gb[threadIdx.x] = g_gb[r];
        s_ga[threadIdx.x] = g_ga[r];
    }
    __syncthreads();

    // field channels for this anchor: base + f*4096
    int base = (b*(NA*NCH) + a*NCH)*HW + ji;
    float o0 = out[base];
    float o1 = out[base +   HW];
    float o2 = out[base + 2*HW];
    float o3 = out[base + 3*HW];
    float o4 = out[base + 4*HW];

    float aw = anchors[2*a], ah = anchors[2*a+1];
    float x    = 1.0f / (1.0f + __expf(-o0));
    float y    = 1.0f / (1.0f + __expf(-o1));
    float conf = 1.0f / (1.0f + __expf(-o4));
    float pw = __expf(o2) * aw;
    float ph = __expf(o3) * ah;
    float px = x + (float)i, py = y + (float)j;
    float pl = px - 0.5f*pw, pr = px + 0.5f*pw;
    float pt = py - 0.5f*ph, pb = py + 0.5f*ph;
    float parea = pw * ph;

    float maxiou = 0.0f;
    int matched = -1;   // last writer wins (ascending t overwrite)
    #pragma unroll 1
    for (int t = 0; t < NT; t++) {
        int c = s_cell[t];
        if (c < 0) continue;                 // uniform within block
        float l  = fmaxf(pl, s_gl[t]);
        float r  = fminf(pr, s_gr[t]);
        float tt = fmaxf(pt, s_gt[t]);
        float bb = fminf(pb, s_gb[t]);
        float inter = fmaxf(r - l, 0.0f) * fmaxf(bb - tt, 0.0f);
        float uni = fmaxf(parea + s_ga[t] - inter, 1e-10f);
        float iou = __fdividef(inter, uni);
        maxiou = fmaxf(maxiou, iou);
        if (c == gid) matched = t;
    }

    float txv = 0.5f, tyv = 0.5f, twv = 0.0f, thv = 0.0f, tconf = 0.0f;
    float cmask = (maxiou > 0.6f) ? 0.0f : 1.0f;   // NOOBJ_SCALE = 1
    float lcls = 0.0f;
    if (matched >= 0) {
        cmask = 5.0f;                               // OBJ_SCALE
        int r = b*NT + matched;
        txv = g_tx[r]; tyv = g_ty[r]; twv = g_twv[r]; thv = g_thv[r];
        // precise IoU(gbox, pred at this cell) for tconf
        float l  = fmaxf(pl, g_gl[r]);
        float rr = fminf(pr, g_gr[r]);
        float tt = fmaxf(pt, g_gt[r]);
        float bb = fminf(pb, g_gb[r]);
        float inter = fmaxf(rr - l, 0.0f) * fmaxf(bb - tt, 0.0f);
        float uni = fmaxf(parea + g_ga[r] - inter, 1e-10f);
        tconf = inter / uni;
        // class NLL at this cell (rare path; ~12 per batch)
        int tcls = g_tcls[r];
        int cbase = base + 5*HW;
        float lg[NC];
        float m = -1e30f;
        #pragma unroll
        for (int c = 0; c < NC; c++) {
            lg[c] = out[cbase + c*HW];
            m = fmaxf(m, lg[c]);
        }
        float s = 0.0f;
        #pragma unroll
        for (int c = 0; c < NC; c++) s += expf(lg[c] - m);
        float lse = m + logf(s);
        lcls = lse - lg[tcls];                      // -(picked)
    }

    float dx = x - txv, dy = y - tyv;
    float dw = o2 - twv, dh = o3 - thv;
    float dc = conf - tconf;
    double local = 0.5 * ((double)(dx*dx) + (double)(dy*dy)
                        + (double)(dw*dw) + (double)(dh*dh)
                        + (double)cmask * (double)(dc*dc))
                 + (double)lcls;

    // block reduction -> one double atomic per block
    double v = local;
    #pragma unroll
    for (int o = 16; o > 0; o >>= 1)
        v += __shfl_down_sync(0xffffffffu, v, o);
    int lane = threadIdx.x & 31, w = threadIdx.x >> 5;
    if (lane == 0) s_ws[w] = v;
    __syncthreads();
    if (w == 0) {
        v = (lane < 8) ? s_ws[lane] : 0.0;
        #pragma unroll
        for (int o = 4; o > 0; o >>= 1)
            v += __shfl_down_sync(0xffffffffu, v, o);
        if (lane == 0) atomicAdd(&g_loss, v);
    }
}

__global__ void k_finish(float* __restrict__ o) {
    if (threadIdx.x == 0) o[0] = (float)g_loss;
}

extern "C" void kernel_launch(void* const* d_in, const int* in_sizes, int n_in,
                              void* d_out, int out_size) {
    const float* output  = (const float*)d_in[0];
    const float* target  = (const float*)d_in[1];
    const float* anchors = (const float*)d_in[2];
    float* out = (float*)d_out;
    (void)in_sizes; (void)n_in; (void)out_size;

    k_zero<<<1, 32>>>();
    k_prep<<<NB, 64>>>(target, anchors);
    k_main<<<NCELL/256, 256>>>(output, anchors);
    k_finish<<<1, 1>>>(out);
}

// round 2
// speedup vs baseline: 1.0558x; 1.0558x over previous
#include <cuda_runtime.h>
#include <math.h>

#define NB 32
#define NA 5
#define NC 20
#define NH 64
#define NW 64
#define NT 50
#define HW (NH*NW)                  // 4096
#define CELLS_PER_B (NA*HW)         // 20480
#define NCELL (NB*CELLS_PER_B)      // 655360
#define NCH (5+NC)                  // 25
#define TPB 256
#define NBLK (NCELL/TPB)            // 2560

// Compacted per-target records (device globals — no allocation allowed)
__device__ int    g_cnt[NB];
__device__ int    g_cell[NB*NT];
__device__ float  g_gl[NB*NT], g_gr[NB*NT], g_gt[NB*NT], g_gb[NB*NT];
__device__ float  g_thr[NB*NT];   // 0.375 * gw*gh  (iou>0.6 test constant)
__device__ float  g_ga[NB*NT];    // gw*gh (for matched precise IoU)
__device__ float  g_tx[NB*NT], g_ty[NB*NT], g_twv[NB*NT], g_thv[NB*NT];
__device__ int    g_tcls[NB*NT];
__device__ double g_part[NBLK];
__device__ int    g_ticket = 0;

// One block per batch; threads 0..49 compute per-target records, then a
// ballot-free serial prefix (thread 0) compacts them preserving t order
// (last-writer-wins semantics depend on ascending order).
__global__ void k_prep(const float* __restrict__ target,
                       const float* __restrict__ anchors) {
    __shared__ int s_slot[NT];
    int b = blockIdx.x;
    int t = threadIdx.x;

    float gx=0, gy=0, gw=0, gh=0, cls=0;
    bool v = false;
    if (t < NT) {
        const float* tg = target + (size_t)(b*NT + t)*5;
        cls = tg[0];
        float xn = tg[1], yn = tg[2], wn = tg[3], hn = tg[4];
        v = (xn > 0.0f);
        gx = xn * (float)NW; gy = yn * (float)NH;
        gw = wn * (float)NW; gh = hn * (float)NH;
        s_slot[t] = v ? 1 : 0;
    }
    __syncthreads();
    if (t == 0) {
        int c = 0;
        #pragma unroll
        for (int i = 0; i < NT; i++) { int f = s_slot[i]; s_slot[i] = c; c += f; }
        g_cnt[b] = c;
    }
    __syncthreads();

    if (v) {
        // best anchor by wh-IoU (first max wins)
        int best = 0; float bi = -1.0f, baw = anchors[0], bah = anchors[1];
        #pragma unroll
        for (int a = 0; a < NA; a++) {
            float aw = anchors[2*a], ah = anchors[2*a+1];
            float inter = fminf(gw, aw) * fminf(gh, ah);
            float uni = fmaxf(gw*gh + aw*ah - inter, 1e-10f);
            float iou = inter / uni;
            if (iou > bi) { bi = iou; best = a; baw = aw; bah = ah; }
        }
        int gi = min(max((int)floorf(gx), 0), NW-1);
        int gj = min(max((int)floorf(gy), 0), NH-1);
        int s = b*NT + s_slot[t];
        g_cell[s] = ((b*NA + best)*NH + gj)*NW + gi;
        g_gl[s] = gx - 0.5f*gw;  g_gr[s] = gx + 0.5f*gw;
        g_gt[s] = gy - 0.5f*gh;  g_gb[s] = gy + 0.5f*gh;
        float area = gw * gh;
        g_ga[s]  = area;
        g_thr[s] = 0.375f * area;
        g_tx[s]  = gx - (float)gi;
        g_ty[s]  = gy - (float)gj;
        g_twv[s] = logf(fmaxf(gw, 1e-10f) / baw);
        g_thv[s] = logf(fmaxf(gh, 1e-10f) / bah);
        g_tcls[s] = (int)cls;
    }
}

// One thread per cell. 20480 % 256 == 0 -> each block lives in one batch;
// target records are uniform per block (SMEM broadcast, no divergence).
__global__ void __launch_bounds__(TPB) k_main(const float* __restrict__ out,
                                              const float* __restrict__ anchors,
                                              float* __restrict__ res) {
    __shared__ int   s_cnt;
    __shared__ int   s_cell[NT];
    __shared__ float s_gl[NT], s_gr[NT], s_gt[NT], s_gb[NT], s_thr[NT];
    __shared__ double s_ws[TPB/32];

    int tid = threadIdx.x;
    int gid = blockIdx.x * TPB + tid;
    int b = gid / CELLS_PER_B;
    int within = gid - b * CELLS_PER_B;
    int a = within >> 12;
    int ji = within & 4095;
    int j = ji >> 6, i = ji & 63;

    if (tid == 0) s_cnt = g_cnt[b];
    __syncthreads();
    int cnt = s_cnt;
    if (tid < cnt) {
        int r = b*NT + tid;
        s_cell[tid] = g_cell[r];
        s_gl[tid] = g_gl[r];   s_gr[tid] = g_gr[r];
        s_gt[tid] = g_gt[r];   s_gb[tid] = g_gb[r];
        s_thr[tid] = g_thr[r];
    }
    __syncthreads();

    int base = (b*(NA*NCH) + a*NCH)*HW + ji;
    float o0 = out[base];
    float o1 = out[base +   HW];
    float o2 = out[base + 2*HW];
    float o3 = out[base + 3*HW];
    float o4 = out[base + 4*HW];

    float aw = anchors[2*a], ah = anchors[2*a+1];
    float x    = 1.0f / (1.0f + __expf(-o0));
    float y    = 1.0f / (1.0f + __expf(-o1));
    float conf = 1.0f / (1.0f + __expf(-o4));
    float pw = __expf(o2) * aw;
    float ph = __expf(o3) * ah;
    float px = x + (float)i, py = y + (float)j;
    float pl = px - 0.5f*pw, pr = px + 0.5f*pw;
    float pt = py - 0.5f*ph, pb = py + 0.5f*ph;
    float parea = pw * ph;
    float pthr  = 0.375f * parea;   // inter > 0.375*(parea+garea) <=> iou > 0.6

    bool sil = false;
    int matched = -1;               // last writer wins (ascending t)
    #pragma unroll 1
    for (int t = 0; t < cnt; t++) {
        float l  = fmaxf(pl, s_gl[t]);
        float r  = fminf(pr, s_gr[t]);
        float tt = fmaxf(pt, s_gt[t]);
        float bb = fminf(pb, s_gb[t]);
        float inter = fmaxf(r - l, 0.0f) * fmaxf(bb - tt, 0.0f);
        sil = sil | (inter > pthr + s_thr[t]);
        if (s_cell[t] == gid) matched = t;
    }

    float txv = 0.5f, tyv = 0.5f, twv = 0.0f, thv = 0.0f, tconf = 0.0f;
    float cmask = sil ? 0.0f : 1.0f;   // NOOBJ_SCALE = 1
    float lcls = 0.0f;
    if (matched >= 0) {
        cmask = 5.0f;                   // OBJ_SCALE
        int r = b*NT + matched;
        txv = g_tx[r]; tyv = g_ty[r]; twv = g_twv[r]; thv = g_thv[r];
        float ga = g_ga[r];
        float l  = fmaxf(pl, g_gl[r]);
        float rr = fminf(pr, g_gr[r]);
        float tt = fmaxf(pt, g_gt[r]);
        float bb = fminf(pb, g_gb[r]);
        float inter = fmaxf(rr - l, 0.0f) * fmaxf(bb - tt, 0.0f);
        float uni = fmaxf(parea + ga - inter, 1e-10f);
        tconf = inter / uni;
        // class NLL at this cell (rare: ~12 cells per batch)
        int tcls = g_tcls[r];
        int cbase = base + 5*HW;
        float lg[NC];
        float m = -1e30f;
        #pragma unroll
        for (int c = 0; c < NC; c++) {
            lg[c] = out[cbase + c*HW];
            m = fmaxf(m, lg[c]);
        }
        float s = 0.0f;
        #pragma unroll
        for (int c = 0; c < NC; c++) s += __expf(lg[c] - m);
        lcls = m + logf(s) - lg[tcls];
    }

    float dx = x - txv, dy = y - tyv;
    float dw = o2 - twv, dh = o3 - thv;
    float dc = conf - tconf;
    double local = 0.5 * ((double)(dx*dx) + (double)(dy*dy)
                        + (double)(dw*dw) + (double)(dh*dh)
                        + (double)cmask * (double)(dc*dc))
                 + (double)lcls;

    // block reduction -> plain partial store (no contended atomics)
    double v = local;
    #pragma unroll
    for (int o = 16; o > 0; o >>= 1)
        v += __shfl_down_sync(0xffffffffu, v, o);
    int lane = tid & 31, w = tid >> 5;
    if (lane == 0) s_ws[w] = v;
    __syncthreads();
    if (w == 0) {
        v = (lane < TPB/32) ? s_ws[lane] : 0.0;
        #pragma unroll
        for (int o = 4; o > 0; o >>= 1)
            v += __shfl_down_sync(0xffffffffu, v, o);
        if (lane == 0) g_part[blockIdx.x] = v;
    }

    // arrival ticket: last block reduces the 2560 partials and writes result
    __shared__ bool s_last;
    __threadfence();
    __syncthreads();
    if (tid == 0) {
        int old = atomicAdd(&g_ticket, 1);
        s_last = (old == NBLK - 1);
    }
    __syncthreads();
    if (s_last) {
        double acc = 0.0;
        for (int idx = tid; idx < NBLK; idx += TPB) acc += g_part[idx];
        #pragma unroll
        for (int o = 16; o > 0; o >>= 1)
            acc += __shfl_down_sync(0xffffffffu, acc, o);
        if (lane == 0) s_ws[w] = acc;
        __syncthreads();
        if (w == 0) {
            acc = (lane < TPB/32) ? s_ws[lane] : 0.0;
            #pragma unroll
            for (int o = 4; o > 0; o >>= 1)
                acc += __shfl_down_sync(0xffffffffu, acc, o);
            if (lane == 0) { res[0] = (float)acc; g_ticket = 0; }
        }
    }
}

extern "C" void kernel_launch(void* const* d_in, const int* in_sizes, int n_in,
                              void* d_out, int out_size) {
    const float* output  = (const float*)d_in[0];
    const float* target  = (const float*)d_in[1];
    const float* anchors = (const float*)d_in[2];
    float* res = (float*)d_out;
    (void)in_sizes; (void)n_in; (void)out_size;

    k_prep<<<NB, 64>>>(target, anchors);
    k_main<<<NBLK, TPB>>>(output, anchors, res);
}

// round 3
// speedup vs baseline: 1.6815x; 1.5926x over previous
#include <cuda_runtime.h>
#include <math.h>

#define NB 32
#define NA 5
#define NC 20
#define NH 64
#define NW 64
#define NT 50
#define HW (NH*NW)                  // 4096
#define CELLS_PER_B (NA*HW)         // 20480
#define NCELL (NB*CELLS_PER_B)      // 655360
#define NCH (5+NC)                  // 25
#define TPB 256
#define CPT 4                       // cells per thread
#define NBLK (NCELL/(TPB*CPT))      // 640

// Compacted per-target records (device globals — no allocation allowed)
__device__ int    g_cnt[NB];
__device__ int    g_cell[NB*NT];
__device__ float  g_gl[NB*NT], g_gr[NB*NT], g_gt[NB*NT], g_gb[NB*NT];
__device__ float  g_thr[NB*NT];   // 0.375 * gw*gh
__device__ float  g_ga[NB*NT];
__device__ float  g_tx[NB*NT], g_ty[NB*NT], g_twv[NB*NT], g_thv[NB*NT];
__device__ int    g_tcls[NB*NT];
__device__ float  g_part[NBLK];
__device__ int    g_ticket = 0;

__global__ void k_prep(const float* __restrict__ target,
                       const float* __restrict__ anchors) {
    __shared__ int s_slot[NT];
    int b = blockIdx.x;
    int t = threadIdx.x;

    float gx=0, gy=0, gw=0, gh=0, cls=0;
    bool v = false;
    if (t < NT) {
        const float* tg = target + (size_t)(b*NT + t)*5;
        cls = tg[0];
        float xn = tg[1], yn = tg[2], wn = tg[3], hn = tg[4];
        v = (xn > 0.0f);
        gx = xn * (float)NW; gy = yn * (float)NH;
        gw = wn * (float)NW; gh = hn * (float)NH;
        s_slot[t] = v ? 1 : 0;
    }
    __syncthreads();
    if (t == 0) {
        int c = 0;
        #pragma unroll
        for (int i = 0; i < NT; i++) { int f = s_slot[i]; s_slot[i] = c; c += f; }
        g_cnt[b] = c;
    }
    __syncthreads();

    if (v) {
        int best = 0; float bi = -1.0f, baw = anchors[0], bah = anchors[1];
        #pragma unroll
        for (int a = 0; a < NA; a++) {
            float aw = anchors[2*a], ah = anchors[2*a+1];
            float inter = fminf(gw, aw) * fminf(gh, ah);
            float uni = fmaxf(gw*gh + aw*ah - inter, 1e-10f);
            float iou = inter / uni;
            if (iou > bi) { bi = iou; best = a; baw = aw; bah = ah; }
        }
        int gi = min(max((int)floorf(gx), 0), NW-1);
        int gj = min(max((int)floorf(gy), 0), NH-1);
        int s = b*NT + s_slot[t];
        g_cell[s] = ((b*NA + best)*NH + gj)*NW + gi;
        g_gl[s] = gx - 0.5f*gw;  g_gr[s] = gx + 0.5f*gw;
        g_gt[s] = gy - 0.5f*gh;  g_gb[s] = gy + 0.5f*gh;
        float area = gw * gh;
        g_ga[s]  = area;
        g_thr[s] = 0.375f * area;
        g_tx[s]  = gx - (float)gi;
        g_ty[s]  = gy - (float)gj;
        g_twv[s] = logf(fmaxf(gw, 1e-10f) / baw);
        g_thv[s] = logf(fmaxf(gh, 1e-10f) / bah);
        g_tcls[s] = (int)cls;
    }
}

__device__ __forceinline__ float fast_sigmoid(float v) {
    return __fdividef(1.0f, 1.0f + __expf(-v));
}

// 4 cells per thread (float4 loads). 20480 % 1024 == 0 -> block within one batch.
__global__ void __launch_bounds__(TPB) k_main(const float* __restrict__ out,
                                              const float* __restrict__ anchors,
                                              float* __restrict__ res) {
    __shared__ int   s_cnt;
    __shared__ int   s_cell[NT];
    __shared__ float s_gl[NT], s_gr[NT], s_gt[NT], s_gb[NT], s_thr[NT];
    __shared__ float s_ws[TPB/32];
    __shared__ bool  s_last;

    int tid = threadIdx.x;
    int gid0 = (blockIdx.x * TPB + tid) * CPT;
    int b = gid0 / CELLS_PER_B;
    int within = gid0 - b * CELLS_PER_B;
    int a = within >> 12;
    int ji = within & 4095;
    int j = ji >> 6, i0 = ji & 63;

    if (tid == 0) s_cnt = g_cnt[b];
    __syncthreads();
    int cnt = s_cnt;
    if (tid < cnt) {
        int r = b*NT + tid;
        s_cell[tid] = g_cell[r];
        s_gl[tid] = g_gl[r];   s_gr[tid] = g_gr[r];
        s_gt[tid] = g_gt[r];   s_gb[tid] = g_gb[r];
        s_thr[tid] = g_thr[r];
    }
    __syncthreads();

    int base = (b*(NA*NCH) + a*NCH)*HW + ji;
    float4 v0 = *(const float4*)(out + base);
    float4 v1 = *(const float4*)(out + base +   HW);
    float4 v2 = *(const float4*)(out + base + 2*HW);
    float4 v3 = *(const float4*)(out + base + 3*HW);
    float4 v4 = *(const float4*)(out + base + 4*HW);

    float o2a[CPT] = {v2.x, v2.y, v2.z, v2.w};
    float o3a[CPT] = {v3.x, v3.y, v3.z, v3.w};
    float xs[CPT]  = {fast_sigmoid(v0.x), fast_sigmoid(v0.y), fast_sigmoid(v0.z), fast_sigmoid(v0.w)};
    float ys[CPT]  = {fast_sigmoid(v1.x), fast_sigmoid(v1.y), fast_sigmoid(v1.z), fast_sigmoid(v1.w)};
    float cf[CPT]  = {fast_sigmoid(v4.x), fast_sigmoid(v4.y), fast_sigmoid(v4.z), fast_sigmoid(v4.w)};

    float aw = anchors[2*a], ah = anchors[2*a+1];
    float pl[CPT], pr[CPT], pt[CPT], pb[CPT], parea[CPT], pthr[CPT];
    #pragma unroll
    for (int c = 0; c < CPT; c++) {
        float pw = __expf(o2a[c]) * aw;
        float ph = __expf(o3a[c]) * ah;
        float px = xs[c] + (float)(i0 + c);
        float py = ys[c] + (float)j;
        pl[c] = px - 0.5f*pw;  pr[c] = px + 0.5f*pw;
        pt[c] = py - 0.5f*ph;  pb[c] = py + 0.5f*ph;
        parea[c] = pw * ph;
        pthr[c]  = 0.375f * parea[c];
    }

    bool sil[CPT] = {false, false, false, false};
    int matched[CPT] = {-1, -1, -1, -1};
    #pragma unroll 1
    for (int t = 0; t < cnt; t++) {
        float gl = s_gl[t], gr = s_gr[t];
        float gt = s_gt[t], gb = s_gb[t];
        float thr = s_thr[t];
        int   cc = s_cell[t];
        #pragma unroll
        for (int c = 0; c < CPT; c++) {
            float l  = fmaxf(pl[c], gl);
            float r  = fminf(pr[c], gr);
            float tt = fmaxf(pt[c], gt);
            float bb = fminf(pb[c], gb);
            float inter = fmaxf(r - l, 0.0f) * fmaxf(bb - tt, 0.0f);
            sil[c] = sil[c] | (inter > pthr[c] + thr);
            if (cc == gid0 + c) matched[c] = t;
        }
    }

    float acc = 0.0f;
    #pragma unroll
    for (int c = 0; c < CPT; c++) {
        float txv = 0.5f, tyv = 0.5f, twv = 0.0f, thv = 0.0f, tconf = 0.0f;
        float cmask = sil[c] ? 0.0f : 1.0f;
        float lcls = 0.0f;
        if (matched[c] >= 0) {
            cmask = 5.0f;
            int r = b*NT + matched[c];
            txv = g_tx[r]; tyv = g_ty[r]; twv = g_twv[r]; thv = g_thv[r];
            float ga = g_ga[r];
            float l  = fmaxf(pl[c], g_gl[r]);
            float rr = fminf(pr[c], g_gr[r]);
            float tt = fmaxf(pt[c], g_gt[r]);
            float bb = fminf(pb[c], g_gb[r]);
            float inter = fmaxf(rr - l, 0.0f) * fmaxf(bb - tt, 0.0f);
            float uni = fmaxf(parea[c] + ga - inter, 1e-10f);
            tconf = __fdividef(inter, uni);
            int tcls = g_tcls[r];
            int cbase = base + c + 5*HW;
            float lg[NC];
            float m = -1e30f;
            #pragma unroll
            for (int q = 0; q < NC; q++) {
                lg[q] = out[cbase + q*HW];
                m = fmaxf(m, lg[q]);
            }
            float s = 0.0f;
            #pragma unroll
            for (int q = 0; q < NC; q++) s += __expf(lg[q] - m);
            lcls = m + logf(s) - lg[tcls];
        }
        float dx = xs[c] - txv, dy = ys[c] - tyv;
        float dw = o2a[c] - twv, dh = o3a[c] - thv;
        float dc = cf[c] - tconf;
        acc += 0.5f*(dx*dx + dy*dy + dw*dw + dh*dh + cmask*(dc*dc)) + lcls;
    }

    // block reduction (fp32) -> one partial per block
    float v = acc;
    #pragma unroll
    for (int o = 16; o > 0; o >>= 1)
        v += __shfl_down_sync(0xffffffffu, v, o);
    int lane = tid & 31, w = tid >> 5;
    if (lane == 0) s_ws[w] = v;
    __syncthreads();
    if (w == 0) {
        v = (lane < TPB/32) ? s_ws[lane] : 0.0f;
        #pragma unroll
        for (int o = 4; o > 0; o >>= 1)
            v += __shfl_down_sync(0xffffffffu, v, o);
        if (lane == 0) g_part[blockIdx.x] = v;
    }

    // arrival ticket: last block sums the 640 partials in double
    __threadfence();
    __syncthreads();
    if (tid == 0) {
        int old = atomicAdd(&g_ticket, 1);
        s_last = (old == NBLK - 1);
    }
    __syncthreads();
    if (s_last) {
        double dacc = 0.0;
        for (int idx = tid; idx < NBLK; idx += TPB) dacc += (double)g_part[idx];
        #pragma unroll
        for (int o = 16; o > 0; o >>= 1)
            dacc += __shfl_down_sync(0xffffffffu, dacc, o);
        __shared__ double s_dw[TPB/32];
        if (lane == 0) s_dw[w] = dacc;
        __syncthreads();
        if (w == 0) {
            dacc = (lane < TPB/32) ? s_dw[lane] : 0.0;
            #pragma unroll
            for (int o = 4; o > 0; o >>= 1)
                dacc += __shfl_down_sync(0xffffffffu, dacc, o);
            if (lane == 0) { res[0] = (float)dacc; g_ticket = 0; }
        }
    }
}

extern "C" void kernel_launch(void* const* d_in, const int* in_sizes, int n_in,
                              void* d_out, int out_size) {
    const float* output  = (const float*)d_in[0];
    const float* target  = (const float*)d_in[1];
    const float* anchors = (const float*)d_in[2];
    float* res = (float*)d_out;
    (void)in_sizes; (void)n_in; (void)out_size;

    k_prep<<<NB, 64>>>(target, anchors);
    k_main<<<NBLK, TPB>>>(output, anchors, res);
}